// round 15
// baseline (speedup 1.0000x reference)
#include <cuda_runtime.h>
#include <math.h>

// Problem constants
#define BB 4
#define H 512
#define W 512
#define HW (H*W)          // 262144
#define NPIX (BB*HW)      // 1048576
#define NSUB 32           // max substeps = 16 Zhang-Suen double-steps (verified exact)
#define TROWS 80          // 16-row band + 32-row halo each side
#define THIN_THREADS 640  // TROWS*8 words, 1 word/thread
#define DR_BLOCKS 512     // k_dist_reduce: one row per block, 256 threads

typedef unsigned long long u64;
typedef unsigned int u32;

// Static device scratch
__device__ __align__(128) u64 g_bits [BB * H * 8];   // input bitboards (1 bit/px)
__device__ __align__(128) u64 g_bits2[BB * H * 8];   // converged skeleton bits
__device__ float  g_sumL[HW];     // L summed over batch (all `base` needs)
__device__ float  g_g2[NPIX];
__device__ double g_partB[DR_BLOCKS];
__device__ int    g_partC[DR_BLOCKS];
__device__ int    g_partD[DR_BLOCKS];
__device__ int    g_ctr = 0;
__device__ int    g_bar = 0;      // software grid barrier counter

// ---------------------------------------------------------------------------
// Kernel 1: CE loss summed over batch (softplus form, 2 MUFU) + bitboards.
// ---------------------------------------------------------------------------
__global__ void k_prep(const float* __restrict__ pred, const int* __restrict__ target)
{
    int t  = blockIdx.x * blockDim.x + threadIdx.x;   // 0..32767
    int i0 = t << 3;

    float sumL[8] = {0,0,0,0,0,0,0,0};

    #pragma unroll
    for (int b = 0; b < BB; b++) {
        const float4* p0v = (const float4*)(pred + (size_t)b * 2 * HW + i0);
        const float4* p1v = (const float4*)(pred + (size_t)b * 2 * HW + HW + i0);
        const int4*   tgv = (const int4*)(target + (size_t)b * HW + i0);
        float4 a0 = p0v[0], a1 = p0v[1];
        float4 b0 = p1v[0], b1 = p1v[1];
        int4   t0 = tgv[0], t1 = tgv[1];

        float p0a[8] = {a0.x,a0.y,a0.z,a0.w, a1.x,a1.y,a1.z,a1.w};
        float p1a[8] = {b0.x,b0.y,b0.z,b0.w, b1.x,b1.y,b1.z,b1.w};
        int   tg[8]  = {t0.x,t0.y,t0.z,t0.w, t1.x,t1.y,t1.z,t1.w};

        u32 bits = 0;
        #pragma unroll
        for (int j = 0; j < 8; j++) {
            float d = tg[j] ? (p0a[j] - p1a[j]) : (p1a[j] - p0a[j]);  // p_other - p_t
            sumL[j] += __logf(1.0f + __expf(d));
            bits |= (p1a[j] > p0a[j] ? 1u : 0u) << j;
        }
        ((unsigned char*)g_bits)[(size_t)b * 32768 + t] = (unsigned char)bits;
    }
    float4* Lv = (float4*)(g_sumL + i0);
    Lv[0] = make_float4(sumL[0], sumL[1], sumL[2], sumL[3]);
    Lv[1] = make_float4(sumL[4], sumL[5], sumL[6], sumL[7]);
}

// ---------------------------------------------------------------------------
// Kernel 2: ALL thinning in one launch (unchanged, rel_err 0.0).
// ---------------------------------------------------------------------------
__global__ void __launch_bounds__(THIN_THREADS, 1) k_thin_all()
{
    __shared__ u64 buf0[THIN_THREADS];
    __shared__ u64 buf1[THIN_THREADS];
    __shared__ int stamp[TROWS + 2];   // stampOf(r) = stamp[r+1], init 0

    int img  = blockIdx.x >> 5;
    int band = blockIdx.x & 31;
    int t    = threadIdx.x;            // 0..639
    int r    = t >> 3;
    int wx   = t & 7;
    const u64* gb = g_bits + (size_t)img * 4096;

    {
        int imr = band * 16 - 32 + r;
        u64 v = (imr >= 0 && imr < H) ? gb[imr * 8 + wx] : 0ULL;
        buf0[t] = v;
        if (r == 0 || r == TROWS - 1) buf1[t] = v;   // edge rows frozen in both buffers
        if (t < TROWS + 2) stamp[t] = 0;
    }
    __syncthreads();

    bool interior = (r >= 1 && r <= TROWS - 2);
    int base = r * 8 + wx;
    u64* fin = buf0;                   // final-state buffer (NSUB even -> buf0)

    #pragma unroll 1
    for (int s = 1; s <= NSUB; s++) {
        const u64* __restrict__ src = (s & 1) ? buf0 : buf1;
        u64* __restrict__ dst       = (s & 1) ? buf1 : buf0;
        bool FIRST = (s & 1);

        bool active = false;
        if (interior) {
            int a0 = stamp[r], a1 = stamp[r + 1], a2 = stamp[r + 2];
            active = (max(a0, max(a1, a2)) >= s - 2);   // parity-correct skip
        }
        if (!__syncthreads_or(active ? 1 : 0)) {        // whole tile converged
            fin = ((s - 1) & 1) ? buf1 : buf0;          // dst of substep s-1 (= state)
            break;
        }

        if (active) {
            u64 ctr = src[base];
            u64 cW = wx      ? src[base - 1] : 0ULL;
            u64 cE = wx < 7  ? src[base + 1] : 0ULL;
            u64 up = src[base - 8];
            u64 uW = wx      ? src[base - 9] : 0ULL;
            u64 uE = wx < 7  ? src[base - 7] : 0ULL;
            u64 dn = src[base + 8];
            u64 dW = wx      ? src[base + 7] : 0ULL;
            u64 dE = wx < 7  ? src[base + 9] : 0ULL;

            u64 P2 = up, P6 = dn;
            u64 P4 = (ctr >> 1) | (cE << 63);
            u64 P8 = (ctr << 1) | (cW >> 63);
            u64 P3 = (up  >> 1) | (uE << 63);
            u64 P9 = (up  << 1) | (uW >> 63);
            u64 P5 = (dn  >> 1) | (dE << 63);
            u64 P7 = (dn  << 1) | (dW >> 63);

            u64 x, y;
            x = P2 ^ P3;            u64 s1a = x ^ P4;  u64 c1a = (P2 & P3) | (P4 & x);
            x = P5 ^ P6;            u64 s1b = x ^ P7;  u64 c1b = (P5 & P6) | (P7 & x);
            x = s1a ^ s1b;          u64 s1c = x ^ P8;  u64 c1c = (s1a & s1b) | (P8 & x);
            u64 s0  = s1c ^ P9;     u64 c1d = s1c & P9;
            y = c1a ^ c1b;          u64 s2a = y ^ c1c; u64 c2a = (c1a & c1b) | (c1c & y);
            u64 sl1 = s2a ^ c1d;    u64 c2b = s2a & c1d;
            u64 sl2 = c2a ^ c2b;    u64 sl3 = c2a & c2b;

            u64 ge2 = sl1 | sl2 | sl3;
            u64 ge7 = sl3 | (sl2 & sl1 & s0);
            u64 in24 = ge2 & ~ge7;

            u64 t1 = ~P2 & P3, t2 = ~P3 & P4, t3 = ~P4 & P5, t4 = ~P5 & P6;
            u64 t5 = ~P6 & P7, t6 = ~P7 & P8, t7 = ~P8 & P9, t8 = ~P9 & P2;
            u64 acc = t1, multi = 0ULL;
            multi |= acc & t2; acc |= t2;
            multi |= acc & t3; acc |= t3;
            multi |= acc & t4; acc |= t4;
            multi |= acc & t5; acc |= t5;
            multi |= acc & t6; acc |= t6;
            multi |= acc & t7; acc |= t7;
            multi |= acc & t8; acc |= t8;
            u64 eq1 = acc & ~multi;

            u64 cc;
            if (FIRST) cc = ~(P2 & P4 & P6) & ~(P4 & P6 & P8);
            else       cc = ~(P2 & P4 & P8) & ~(P2 & P6 & P8);

            u64 rem = ctr & in24 & eq1 & cc;
            dst[base] = ctr ^ rem;
            if (rem) stamp[r + 1] = s;   // benign race (same value)
        }
        __syncthreads();
    }

    // output band = tile rows [32,48) of fin
    if (t < 128) {
        int rr = 32 + (t >> 3);
        int ww = t & 7;
        int imr = band * 16 + (t >> 3);
        g_bits2[(size_t)img * 4096 + imr * 8 + ww] = fin[rr * 8 + ww];
    }
}

// ---------------------------------------------------------------------------
// Kernel 3: FUSED vscan + row EDT + LUT neighborhood + base + final sum.
// 512 blocks x 256 threads, __launch_bounds__(256,4) => >=4 blocks/SM =>
// >=592 resident slots >= 512 blocks: software grid barrier is deadlock-free.
// Phase A: warps gw<2048 run the exact capped vertical scan (bit-identical).
// Barrier (threadfence + atomic arrive + spin + threadfence).
// Phase B: one row per block, 2 pixels/thread, R13's per-radius-break EDT.
// ---------------------------------------------------------------------------
__global__ void __launch_bounds__(256, 4) k_dist_reduce(float* __restrict__ out)
{
    __shared__ float4 sg4[W];             // 8 KB: g2 row, batch-interleaved
    __shared__ u64    sbW[BB][3][9];      // west-shifted rows (+1 virtual word)
    __shared__ u32    lut[512];
    __shared__ double redB[8], redC[8], redD[8];
    __shared__ int    isLast;

    int t = threadIdx.x;                  // 0..255

    // ---------------- Phase A: vscan (warp-per-column, gw<2048) ----------
    {
        int gw   = blockIdx.x * 8 + (t >> 5);
        int lane = t & 31;
        if (gw < 2048) {
            int b = gw >> 9;
            int w = gw & (W - 1);
            const u64* __restrict__ bits = g_bits2 + (size_t)b * 4096;
            float* __restrict__ g2 = g_g2 + (size_t)b * HW;
            int wx = w >> 6, bi = w & 63;

            int base_row = lane * 16;
            int v[16];
            #pragma unroll
            for (int k = 0; k < 16; k++)
                v[k] = (int)((bits[(base_row + k) * 8 + wx] >> bi) & 1ULL);

            int ll = -100000;
            #pragma unroll
            for (int k = 0; k < 16; k++) if (v[k]) ll = base_row + k;
            int incl = ll;
            #pragma unroll
            for (int o = 1; o < 32; o <<= 1) {
                int x = __shfl_up_sync(0xffffffffu, incl, o);
                if (lane >= o) incl = max(incl, x);
            }
            int prefix = __shfl_up_sync(0xffffffffu, incl, 1);
            if (lane == 0) prefix = -100000;

            int lf = 100000;
            #pragma unroll
            for (int k = 15; k >= 0; k--) if (v[k]) lf = base_row + k;
            int incl2 = lf;
            #pragma unroll
            for (int o = 1; o < 32; o <<= 1) {
                int x = __shfl_down_sync(0xffffffffu, incl2, o);
                if (lane < 32 - o) incl2 = min(incl2, x);
            }
            int suffix = __shfl_down_sync(0xffffffffu, incl2, 1);
            if (lane == 31) suffix = 100000;

            int nxt[16];
            int cur = suffix;
            #pragma unroll
            for (int k = 15; k >= 0; k--) {
                int idx = base_row + k;
                if (v[k]) cur = idx;
                nxt[k] = cur;
            }
            int last = prefix;
            #pragma unroll
            for (int k = 0; k < 16; k++) {
                int idx = base_row + k;
                if (v[k]) last = idx;
                float fd = fminf((float)(idx - last), 1024.0f);
                float bd = fminf((float)(nxt[k] - idx), 1024.0f);
                float d  = fminf(fd, bd);
                g2[idx * W + w] = d * d;
            }
        }
    }

    // ---------------- software grid barrier ------------------------------
    __threadfence();
    __syncthreads();
    if (t == 0) {
        atomicAdd(&g_bar, 1);
        while (atomicAdd(&g_bar, 0) < DR_BLOCKS) { __nanosleep(60); }
    }
    __syncthreads();
    __threadfence();

    // ---------------- Phase B: row EDT + neighborhood + reduce -----------
    int h = blockIdx.x;

    #pragma unroll
    for (int k = 0; k < 2; k++) {
        int q = t + k * 256;
        float4 g;
        g.x = g_g2[0 * HW + h * W + q];
        g.y = g_g2[1 * HW + h * W + q];
        g.z = g_g2[2 * HW + h * W + q];
        g.w = g_g2[3 * HW + h * W + q];
        sg4[q] = g;

        // 9-bit neighborhood LUT: bit0..2 = P9,P2,P3; 3..5 = P8,s,P4; 6..8 = P7,P6,P5
        int key = q;
        int s   = (key >> 4) & 1;
        int cnt = __popc(key) - s;
        int rh  = __popc(key & 0x38);
        int rv  = ((key >> 1) & 1) + s + ((key >> 7) & 1);
        int rd1 = (key & 1)        + s + ((key >> 8) & 1);
        int rd2 = ((key >> 2) & 1) + s + ((key >> 6) & 1);
        int dl  = abs(1 - rh) + abs(1 - rv) + abs(1 - rd1) + abs(1 - rd2);
        int e   = (s && (cnt == 1 || cnt >= 3)) ? 1 : 0;
        lut[q]  = (u32)(cnt | (dl << 4) | (e << 8));
    }
    if (t < 108) {
        int b = t / 27, rm = t % 27, rr = rm / 9, ww2 = rm % 9;
        int imr = h - 1 + rr;
        u64 m = 0, p = 0;
        if (imr >= 0 && imr < H) {
            const u64* rowp = g_bits2 + (size_t)b * 4096 + imr * 8;
            m = (ww2 < 8) ? rowp[ww2]     : 0ULL;
            p = (ww2 > 0) ? rowp[ww2 - 1] : 0ULL;
        }
        sbW[b][rr][ww2] = (m << 1) | (p >> 63);   // bit j = pixel j-1
    }
    __syncthreads();

    double sbAcc = 0.0;
    int contI = 0, dirlI = 0;

    #pragma unroll 1
    for (int k = 0; k < 2; k++) {
        int w = t + k * 256;

        // interleaved 4-batch expanding-search EDT (per-batch order bit-exact)
        float4 dd = sg4[w];
        {
            float m = fmaxf(fmaxf(dd.x, dd.y), fmaxf(dd.z, dd.w));
            for (int r = 1; r < W; r++) {
                float rr = (float)(r * r);
                if (rr >= m) break;
                int ql = w - r, qr = w + r;
                if (ql >= 0) {
                    float4 v = sg4[ql];
                    dd.x = fminf(dd.x, v.x + rr);
                    dd.y = fminf(dd.y, v.y + rr);
                    dd.z = fminf(dd.z, v.z + rr);
                    dd.w = fminf(dd.w, v.w + rr);
                }
                if (qr < W) {
                    float4 v = sg4[qr];
                    dd.x = fminf(dd.x, v.x + rr);
                    dd.y = fminf(dd.y, v.y + rr);
                    dd.z = fminf(dd.z, v.z + rr);
                    dd.w = fminf(dd.w, v.w + rr);
                }
                m = fmaxf(fmaxf(dd.x, dd.y), fmaxf(dd.z, dd.w));
            }
        }
        float wex[4] = { __expf(sqrtf(dd.x) * -0.05f), __expf(sqrtf(dd.y) * -0.05f),
                         __expf(sqrtf(dd.z) * -0.05f), __expf(sqrtf(dd.w) * -0.05f) };

        int wx = w >> 6, bi = w & 63;
        float sumW = 0.0f;
        #pragma unroll
        for (int b = 0; b < BB; b++) {
            int key;
            u64 uW = sbW[b][0][wx], cW = sbW[b][1][wx], dW = sbW[b][2][wx];
            if (bi < 62) {
                key = (int)((uW >> bi) & 7)
                    | ((int)((cW >> bi) & 7) << 3)
                    | ((int)((dW >> bi) & 7) << 6);
            } else {
                u64 uN = sbW[b][0][wx + 1], cN = sbW[b][1][wx + 1], dN = sbW[b][2][wx + 1];
                int sh2 = 64 - bi;   // 1 or 2
                key = (int)(((uW >> bi) | (uN << sh2)) & 7)
                    | ((int)(((cW >> bi) | (cN << sh2)) & 7) << 3)
                    | ((int)(((dW >> bi) | (dN << sh2)) & 7) << 6);
            }
            u32 v = lut[key];
            contI += (int)(v & 15);
            dirlI += (int)((v >> 4) & 15);
            sumW  += wex[b] + ((v & 256) ? 20.0f : 0.0f);
        }
        sbAcc += (double)sumW * (double)g_sumL[h * W + w];
    }

    double sb = sbAcc;
    unsigned fm = 0xffffffffu;
    double sc = (double)contI, sd = (double)dirlI;
    #pragma unroll
    for (int o = 16; o > 0; o >>= 1) {
        sb += __shfl_down_sync(fm, sb, o);
        sc += __shfl_down_sync(fm, sc, o);
        sd += __shfl_down_sync(fm, sd, o);
    }
    int wid = t >> 5, lane = t & 31;
    if (lane == 0) { redB[wid] = sb; redC[wid] = sc; redD[wid] = sd; }
    __syncthreads();
    if (wid == 0) {
        double b2 = (lane < 8) ? redB[lane] : 0.0;
        double c2 = (lane < 8) ? redC[lane] : 0.0;
        double d2 = (lane < 8) ? redD[lane] : 0.0;
        #pragma unroll
        for (int o = 4; o > 0; o >>= 1) {
            b2 += __shfl_down_sync(fm, b2, o);
            c2 += __shfl_down_sync(fm, c2, o);
            d2 += __shfl_down_sync(fm, d2, o);
        }
        if (lane == 0) {
            g_partB[blockIdx.x] = b2;
            g_partC[blockIdx.x] = (int)c2;
            g_partD[blockIdx.x] = (int)d2;
            __threadfence();
            int old = atomicAdd(&g_ctr, 1);
            isLast = (old == DR_BLOCKS - 1) ? 1 : 0;
        }
    }
    __syncthreads();

    if (isLast) {   // last block: deterministic fixed-order final sum
        __threadfence();
        double b3 = 0.0, c3 = 0.0, d3 = 0.0;
        #pragma unroll
        for (int k = 0; k < 2; k++) {
            int i = t + k * 256;
            b3 += g_partB[i];
            c3 += (double)g_partC[i];
            d3 += (double)g_partD[i];
        }
        #pragma unroll
        for (int o = 16; o > 0; o >>= 1) {
            b3 += __shfl_down_sync(fm, b3, o);
            c3 += __shfl_down_sync(fm, c3, o);
            d3 += __shfl_down_sync(fm, d3, o);
        }
        if (lane == 0) { redB[wid] = b3; redC[wid] = c3; redD[wid] = d3; }
        __syncthreads();
        if (wid == 0) {
            double b4 = (lane < 8) ? redB[lane] : 0.0;
            double c4 = (lane < 8) ? redC[lane] : 0.0;
            double d4 = (lane < 8) ? redD[lane] : 0.0;
            #pragma unroll
            for (int o = 4; o > 0; o >>= 1) {
                b4 += __shfl_down_sync(fm, b4, o);
                c4 += __shfl_down_sync(fm, c4, o);
                d4 += __shfl_down_sync(fm, d4, o);
            }
            if (lane == 0) {
                double base = b4 / (double)((double)BB * BB * HW);
                double cont = c4 / (double)NPIX;
                double dirl = d4 / (double)NPIX;
                out[0] = (float)(base + 0.3 * cont + 0.5 * dirl);
                g_ctr = 0;   // reset for next graph replay
                g_bar = 0;   // reset barrier for next graph replay
            }
        }
    }
}

// ---------------------------------------------------------------------------
extern "C" void kernel_launch(void* const* d_in, const int* in_sizes, int n_in,
                              void* d_out, int out_size)
{
    const float* pred   = (const float*)d_in[0];
    const int*   target = (const int*)d_in[1];

    k_prep<<<128, 256>>>(pred, target);
    k_thin_all<<<128, THIN_THREADS>>>();
    k_dist_reduce<<<DR_BLOCKS, 256>>>((float*)d_out);
}

// round 16
// speedup vs baseline: 1.1668x; 1.1668x over previous
#include <cuda_runtime.h>
#include <math.h>

// Problem constants
#define BB 4
#define H 512
#define W 512
#define HW (H*W)          // 262144
#define NPIX (BB*HW)      // 1048576
#define NSUB 32           // max substeps = 16 Zhang-Suen double-steps (verified exact)
#define TROWS 80          // 16-row band + 32-row halo each side
#define THIN_THREADS 640  // TROWS*8 words, 1 word/thread
#define EDT_BLOCKS 1024   // 2 blocks per row, 256 threads each

typedef unsigned long long u64;
typedef unsigned int u32;

// Static device scratch
__device__ __align__(128) u64 g_bits [BB * H * 8];   // input bitboards (1 bit/px)
__device__ __align__(128) u64 g_bits2[BB * H * 8];   // converged skeleton bits
__device__ float  g_sumL[HW];     // L summed over batch (all `base` needs)
__device__ float  g_g2[NPIX];
__device__ double g_partB[EDT_BLOCKS];
__device__ int    g_partC[EDT_BLOCKS];
__device__ int    g_partD[EDT_BLOCKS];
__device__ int    g_ctr = 0;

// ---------------------------------------------------------------------------
// Kernel 1: CE loss summed over batch (softplus, 2 MUFU) + bitboards.
// 4 pixels/thread (65536 threads -> high occupancy, DRAM-bound). Adjacent
// even/odd lanes pack their nibbles into one bitboard byte via shfl.
// Per-pixel math and b-ascending accumulation identical to the 8px version.
// ---------------------------------------------------------------------------
__global__ void k_prep(const float* __restrict__ pred, const int* __restrict__ target)
{
    int t  = blockIdx.x * blockDim.x + threadIdx.x;   // 0..65535
    int i0 = t << 2;                                   // 4-pixel group

    float sumL[4] = {0,0,0,0};

    #pragma unroll
    for (int b = 0; b < BB; b++) {
        float4 p0 = *(const float4*)(pred + (size_t)b * 2 * HW + i0);
        float4 p1 = *(const float4*)(pred + (size_t)b * 2 * HW + HW + i0);
        int4   tg = *(const int4*)(target + (size_t)b * HW + i0);

        float p0a[4] = {p0.x, p0.y, p0.z, p0.w};
        float p1a[4] = {p1.x, p1.y, p1.z, p1.w};
        int   tga[4] = {tg.x, tg.y, tg.z, tg.w};

        u32 nib = 0;
        #pragma unroll
        for (int j = 0; j < 4; j++) {
            float d = tga[j] ? (p0a[j] - p1a[j]) : (p1a[j] - p0a[j]);  // p_other - p_t
            sumL[j] += __logf(1.0f + __expf(d));
            nib |= (p1a[j] > p0a[j] ? 1u : 0u) << j;
        }
        u32 hi = __shfl_down_sync(0xffffffffu, nib, 1);   // odd lane's nibble
        if ((t & 1) == 0) {
            int q = t >> 1;                                // byte index (8 pixels)
            ((unsigned char*)g_bits)[(size_t)b * 32768 + q] = (unsigned char)(nib | (hi << 4));
        }
    }
    *(float4*)(g_sumL + i0) = make_float4(sumL[0], sumL[1], sumL[2], sumL[3]);
}

// ---------------------------------------------------------------------------
// Kernel 2: ALL thinning in one launch (unchanged, rel_err 0.0).
// ---------------------------------------------------------------------------
__global__ void __launch_bounds__(THIN_THREADS, 1) k_thin_all()
{
    __shared__ u64 buf0[THIN_THREADS];
    __shared__ u64 buf1[THIN_THREADS];
    __shared__ int stamp[TROWS + 2];   // stampOf(r) = stamp[r+1], init 0

    int img  = blockIdx.x >> 5;
    int band = blockIdx.x & 31;
    int t    = threadIdx.x;            // 0..639
    int r    = t >> 3;
    int wx   = t & 7;
    const u64* gb = g_bits + (size_t)img * 4096;

    {
        int imr = band * 16 - 32 + r;
        u64 v = (imr >= 0 && imr < H) ? gb[imr * 8 + wx] : 0ULL;
        buf0[t] = v;
        if (r == 0 || r == TROWS - 1) buf1[t] = v;   // edge rows frozen in both buffers
        if (t < TROWS + 2) stamp[t] = 0;
    }
    __syncthreads();

    bool interior = (r >= 1 && r <= TROWS - 2);
    int base = r * 8 + wx;
    u64* fin = buf0;                   // final-state buffer (NSUB even -> buf0)

    #pragma unroll 1
    for (int s = 1; s <= NSUB; s++) {
        const u64* __restrict__ src = (s & 1) ? buf0 : buf1;
        u64* __restrict__ dst       = (s & 1) ? buf1 : buf0;
        bool FIRST = (s & 1);

        bool active = false;
        if (interior) {
            int a0 = stamp[r], a1 = stamp[r + 1], a2 = stamp[r + 2];
            active = (max(a0, max(a1, a2)) >= s - 2);   // parity-correct skip
        }
        if (!__syncthreads_or(active ? 1 : 0)) {        // whole tile converged
            fin = ((s - 1) & 1) ? buf1 : buf0;          // dst of substep s-1 (= state)
            break;
        }

        if (active) {
            u64 ctr = src[base];
            u64 cW = wx      ? src[base - 1] : 0ULL;
            u64 cE = wx < 7  ? src[base + 1] : 0ULL;
            u64 up = src[base - 8];
            u64 uW = wx      ? src[base - 9] : 0ULL;
            u64 uE = wx < 7  ? src[base - 7] : 0ULL;
            u64 dn = src[base + 8];
            u64 dW = wx      ? src[base + 7] : 0ULL;
            u64 dE = wx < 7  ? src[base + 9] : 0ULL;

            u64 P2 = up, P6 = dn;
            u64 P4 = (ctr >> 1) | (cE << 63);
            u64 P8 = (ctr << 1) | (cW >> 63);
            u64 P3 = (up  >> 1) | (uE << 63);
            u64 P9 = (up  << 1) | (uW >> 63);
            u64 P5 = (dn  >> 1) | (dE << 63);
            u64 P7 = (dn  << 1) | (dW >> 63);

            u64 x, y;
            x = P2 ^ P3;            u64 s1a = x ^ P4;  u64 c1a = (P2 & P3) | (P4 & x);
            x = P5 ^ P6;            u64 s1b = x ^ P7;  u64 c1b = (P5 & P6) | (P7 & x);
            x = s1a ^ s1b;          u64 s1c = x ^ P8;  u64 c1c = (s1a & s1b) | (P8 & x);
            u64 s0  = s1c ^ P9;     u64 c1d = s1c & P9;
            y = c1a ^ c1b;          u64 s2a = y ^ c1c; u64 c2a = (c1a & c1b) | (c1c & y);
            u64 sl1 = s2a ^ c1d;    u64 c2b = s2a & c1d;
            u64 sl2 = c2a ^ c2b;    u64 sl3 = c2a & c2b;

            u64 ge2 = sl1 | sl2 | sl3;
            u64 ge7 = sl3 | (sl2 & sl1 & s0);
            u64 in24 = ge2 & ~ge7;

            u64 t1 = ~P2 & P3, t2 = ~P3 & P4, t3 = ~P4 & P5, t4 = ~P5 & P6;
            u64 t5 = ~P6 & P7, t6 = ~P7 & P8, t7 = ~P8 & P9, t8 = ~P9 & P2;
            u64 acc = t1, multi = 0ULL;
            multi |= acc & t2; acc |= t2;
            multi |= acc & t3; acc |= t3;
            multi |= acc & t4; acc |= t4;
            multi |= acc & t5; acc |= t5;
            multi |= acc & t6; acc |= t6;
            multi |= acc & t7; acc |= t7;
            multi |= acc & t8; acc |= t8;
            u64 eq1 = acc & ~multi;

            u64 cc;
            if (FIRST) cc = ~(P2 & P4 & P6) & ~(P4 & P6 & P8);
            else       cc = ~(P2 & P4 & P8) & ~(P2 & P6 & P8);

            u64 rem = ctr & in24 & eq1 & cc;
            dst[base] = ctr ^ rem;
            if (rem) stamp[r + 1] = s;   // benign race (same value)
        }
        __syncthreads();
    }

    // output band = tile rows [32,48) of fin
    if (t < 128) {
        int rr = 32 + (t >> 3);
        int ww = t & 7;
        int imr = band * 16 + (t >> 3);
        g_bits2[(size_t)img * 4096 + imr * 8 + ww] = fin[rr * 8 + ww];
    }
}

// ---------------------------------------------------------------------------
// Kernel 3: warp-per-column capped vertical distance from bits -> g2 = d^2.
// ---------------------------------------------------------------------------
__global__ void k_vscan()
{
    int gw   = (blockIdx.x * blockDim.x + threadIdx.x) >> 5;  // 0..2047
    int lane = threadIdx.x & 31;
    int b = gw >> 9;
    int w = gw & (W - 1);
    const u64* __restrict__ bits = g_bits2 + (size_t)b * 4096;
    float* __restrict__ g2 = g_g2 + (size_t)b * HW;
    int wx = w >> 6, bi = w & 63;

    int base_row = lane * 16;
    int v[16];
    #pragma unroll
    for (int k = 0; k < 16; k++)
        v[k] = (int)((bits[(base_row + k) * 8 + wx] >> bi) & 1ULL);

    int ll = -100000;
    #pragma unroll
    for (int k = 0; k < 16; k++) if (v[k]) ll = base_row + k;
    int incl = ll;
    #pragma unroll
    for (int o = 1; o < 32; o <<= 1) {
        int x = __shfl_up_sync(0xffffffffu, incl, o);
        if (lane >= o) incl = max(incl, x);
    }
    int prefix = __shfl_up_sync(0xffffffffu, incl, 1);
    if (lane == 0) prefix = -100000;

    int lf = 100000;
    #pragma unroll
    for (int k = 15; k >= 0; k--) if (v[k]) lf = base_row + k;
    int incl2 = lf;
    #pragma unroll
    for (int o = 1; o < 32; o <<= 1) {
        int x = __shfl_down_sync(0xffffffffu, incl2, o);
        if (lane < 32 - o) incl2 = min(incl2, x);
    }
    int suffix = __shfl_down_sync(0xffffffffu, incl2, 1);
    if (lane == 31) suffix = 100000;

    int nxt[16];
    int cur = suffix;
    #pragma unroll
    for (int k = 15; k >= 0; k--) {
        int idx = base_row + k;
        if (v[k]) cur = idx;
        nxt[k] = cur;
    }
    int last = prefix;
    #pragma unroll
    for (int k = 0; k < 16; k++) {
        int idx = base_row + k;
        if (v[k]) last = idx;
        float fd = fminf((float)(idx - last), 1024.0f);
        float bd = fminf((float)(nxt[k] - idx), 1024.0f);
        float d  = fminf(fd, bd);
        g2[idx * W + w] = d * d;
    }
}

// ---------------------------------------------------------------------------
// Kernel 4: FUSED row EDT + LUT neighborhood + broadcast base + final sum.
// 1024 blocks x 256 threads (R13 shape), per-radius break loop (R13 exact).
// ---------------------------------------------------------------------------
__global__ void __launch_bounds__(256) k_edt_reduce(float* __restrict__ out)
{
    __shared__ float4 sg4[W];             // 8 KB: g2 row, batch-interleaved
    __shared__ u64    sbW[BB][3][9];      // west-shifted rows (+1 virtual word)
    __shared__ u32    lut[512];
    __shared__ double redB[8], redC[8], redD[8];
    __shared__ int    isLast;

    int h    = blockIdx.x >> 1;
    int half = blockIdx.x & 1;
    int t    = threadIdx.x;               // 0..255
    int w    = (half << 8) | t;           // this thread's pixel

    #pragma unroll
    for (int k = 0; k < 2; k++) {
        int q = t + k * 256;
        float4 g;
        g.x = g_g2[0 * HW + h * W + q];
        g.y = g_g2[1 * HW + h * W + q];
        g.z = g_g2[2 * HW + h * W + q];
        g.w = g_g2[3 * HW + h * W + q];
        sg4[q] = g;

        // 9-bit neighborhood LUT: bit0..2 = P9,P2,P3; 3..5 = P8,s,P4; 6..8 = P7,P6,P5
        int key = q;
        int s   = (key >> 4) & 1;
        int cnt = __popc(key) - s;
        int rh  = __popc(key & 0x38);
        int rv  = ((key >> 1) & 1) + s + ((key >> 7) & 1);
        int rd1 = (key & 1)        + s + ((key >> 8) & 1);
        int rd2 = ((key >> 2) & 1) + s + ((key >> 6) & 1);
        int dl  = abs(1 - rh) + abs(1 - rv) + abs(1 - rd1) + abs(1 - rd2);
        int e   = (s && (cnt == 1 || cnt >= 3)) ? 1 : 0;
        lut[q]  = (u32)(cnt | (dl << 4) | (e << 8));
    }
    if (t < 108) {
        int b = t / 27, rm = t % 27, rr = rm / 9, ww2 = rm % 9;
        int imr = h - 1 + rr;
        u64 m = 0, p = 0;
        if (imr >= 0 && imr < H) {
            const u64* rowp = g_bits2 + (size_t)b * 4096 + imr * 8;
            m = (ww2 < 8) ? rowp[ww2]     : 0ULL;
            p = (ww2 > 0) ? rowp[ww2 - 1] : 0ULL;
        }
        sbW[b][rr][ww2] = (m << 1) | (p >> 63);   // bit j = pixel j-1
    }
    __syncthreads();

    // interleaved 4-batch expanding-search EDT (per-batch fmin order bit-exact)
    float4 dd = sg4[w];
    {
        float m = fmaxf(fmaxf(dd.x, dd.y), fmaxf(dd.z, dd.w));
        for (int r = 1; r < W; r++) {
            float rr = (float)(r * r);
            if (rr >= m) break;
            int ql = w - r, qr = w + r;
            if (ql >= 0) {
                float4 v = sg4[ql];
                dd.x = fminf(dd.x, v.x + rr);
                dd.y = fminf(dd.y, v.y + rr);
                dd.z = fminf(dd.z, v.z + rr);
                dd.w = fminf(dd.w, v.w + rr);
            }
            if (qr < W) {
                float4 v = sg4[qr];
                dd.x = fminf(dd.x, v.x + rr);
                dd.y = fminf(dd.y, v.y + rr);
                dd.z = fminf(dd.z, v.z + rr);
                dd.w = fminf(dd.w, v.w + rr);
            }
            m = fmaxf(fmaxf(dd.x, dd.y), fmaxf(dd.z, dd.w));
        }
    }
    float wex[4] = { __expf(sqrtf(dd.x) * -0.05f), __expf(sqrtf(dd.y) * -0.05f),
                     __expf(sqrtf(dd.z) * -0.05f), __expf(sqrtf(dd.w) * -0.05f) };

    int wx = w >> 6, bi = w & 63;
    float sumW = 0.0f;
    int contI = 0, dirlI = 0;

    #pragma unroll
    for (int b = 0; b < BB; b++) {
        int key;
        u64 uW = sbW[b][0][wx], cW = sbW[b][1][wx], dW = sbW[b][2][wx];
        if (bi < 62) {
            key = (int)((uW >> bi) & 7)
                | ((int)((cW >> bi) & 7) << 3)
                | ((int)((dW >> bi) & 7) << 6);
        } else {
            u64 uN = sbW[b][0][wx + 1], cN = sbW[b][1][wx + 1], dN = sbW[b][2][wx + 1];
            int sh2 = 64 - bi;   // 1 or 2
            key = (int)(((uW >> bi) | (uN << sh2)) & 7)
                | ((int)(((cW >> bi) | (cN << sh2)) & 7) << 3)
                | ((int)(((dW >> bi) | (dN << sh2)) & 7) << 6);
        }
        u32 v = lut[key];
        contI += (int)(v & 15);
        dirlI += (int)((v >> 4) & 15);
        sumW  += wex[b] + ((v & 256) ? 20.0f : 0.0f);
    }

    double sb = (double)sumW * (double)g_sumL[h * W + w];
    unsigned fm = 0xffffffffu;
    double sc = (double)contI, sd = (double)dirlI;
    #pragma unroll
    for (int o = 16; o > 0; o >>= 1) {
        sb += __shfl_down_sync(fm, sb, o);
        sc += __shfl_down_sync(fm, sc, o);
        sd += __shfl_down_sync(fm, sd, o);
    }
    int wid = t >> 5, lane = t & 31;
    if (lane == 0) { redB[wid] = sb; redC[wid] = sc; redD[wid] = sd; }
    __syncthreads();
    if (wid == 0) {
        double b2 = (lane < 8) ? redB[lane] : 0.0;
        double c2 = (lane < 8) ? redC[lane] : 0.0;
        double d2 = (lane < 8) ? redD[lane] : 0.0;
        #pragma unroll
        for (int o = 4; o > 0; o >>= 1) {
            b2 += __shfl_down_sync(fm, b2, o);
            c2 += __shfl_down_sync(fm, c2, o);
            d2 += __shfl_down_sync(fm, d2, o);
        }
        if (lane == 0) {
            g_partB[blockIdx.x] = b2;
            g_partC[blockIdx.x] = (int)c2;
            g_partD[blockIdx.x] = (int)d2;
            __threadfence();
            int old = atomicAdd(&g_ctr, 1);
            isLast = (old == EDT_BLOCKS - 1) ? 1 : 0;
        }
    }
    __syncthreads();

    if (isLast) {   // last block: deterministic fixed-order final sum
        __threadfence();
        double b3 = 0.0, c3 = 0.0, d3 = 0.0;
        #pragma unroll
        for (int k = 0; k < 4; k++) {
            int i = t + k * 256;
            b3 += g_partB[i];
            c3 += (double)g_partC[i];
            d3 += (double)g_partD[i];
        }
        #pragma unroll
        for (int o = 16; o > 0; o >>= 1) {
            b3 += __shfl_down_sync(fm, b3, o);
            c3 += __shfl_down_sync(fm, c3, o);
            d3 += __shfl_down_sync(fm, d3, o);
        }
        if (lane == 0) { redB[wid] = b3; redC[wid] = c3; redD[wid] = d3; }
        __syncthreads();
        if (wid == 0) {
            double b4 = (lane < 8) ? redB[lane] : 0.0;
            double c4 = (lane < 8) ? redC[lane] : 0.0;
            double d4 = (lane < 8) ? redD[lane] : 0.0;
            #pragma unroll
            for (int o = 4; o > 0; o >>= 1) {
                b4 += __shfl_down_sync(fm, b4, o);
                c4 += __shfl_down_sync(fm, c4, o);
                d4 += __shfl_down_sync(fm, d4, o);
            }
            if (lane == 0) {
                double base = b4 / (double)((double)BB * BB * HW);
                double cont = c4 / (double)NPIX;
                double dirl = d4 / (double)NPIX;
                out[0] = (float)(base + 0.3 * cont + 0.5 * dirl);
                g_ctr = 0;   // reset for next graph replay
            }
        }
    }
}

// ---------------------------------------------------------------------------
extern "C" void kernel_launch(void* const* d_in, const int* in_sizes, int n_in,
                              void* d_out, int out_size)
{
    const float* pred   = (const float*)d_in[0];
    const int*   target = (const int*)d_in[1];

    k_prep<<<256, 256>>>(pred, target);
    k_thin_all<<<128, THIN_THREADS>>>();
    k_vscan<<<256, 256>>>();
    k_edt_reduce<<<EDT_BLOCKS, 256>>>((float*)d_out);
}

// round 17
// speedup vs baseline: 1.2293x; 1.0535x over previous
#include <cuda_runtime.h>
#include <math.h>

// Problem constants
#define BB 4
#define H 512
#define W 512
#define HW (H*W)          // 262144
#define NPIX (BB*HW)      // 1048576
#define NSUB 32           // max substeps = 16 Zhang-Suen double-steps (verified exact)
#define TROWS 80          // 16-row band + 32-row halo each side
#define THIN_THREADS 640  // TROWS*8 words, 1 word/thread
#define EDT_BLOCKS 1024   // 2 blocks per row, 256 threads each

typedef unsigned long long u64;
typedef unsigned int u32;

// Wait for the programmatic-launch predecessor's completion (PDL).
#define GRIDDEP_WAIT() asm volatile("griddepcontrol.wait;" ::: "memory")

// Static device scratch
__device__ __align__(128) u64 g_bits [BB * H * 8];   // input bitboards (1 bit/px)
__device__ __align__(128) u64 g_bits2[BB * H * 8];   // converged skeleton bits
__device__ float  g_sumL[HW];     // L summed over batch (all `base` needs)
__device__ float  g_g2[NPIX];
__device__ double g_partB[EDT_BLOCKS];
__device__ int    g_partC[EDT_BLOCKS];
__device__ int    g_partD[EDT_BLOCKS];
__device__ int    g_ctr = 0;

// ---------------------------------------------------------------------------
// Kernel 1: CE loss summed over batch (softplus, 2 MUFU) + bitboards.
// 4 pixels/thread. Launched WITHOUT PDL (full serialization) so replay N+1
// cannot overlap replay N's edt_reduce reads of g_sumL / g_ctr reset.
// ---------------------------------------------------------------------------
__global__ void k_prep(const float* __restrict__ pred, const int* __restrict__ target)
{
    int t  = blockIdx.x * blockDim.x + threadIdx.x;   // 0..65535
    int i0 = t << 2;                                   // 4-pixel group

    float sumL[4] = {0,0,0,0};

    #pragma unroll
    for (int b = 0; b < BB; b++) {
        float4 p0 = *(const float4*)(pred + (size_t)b * 2 * HW + i0);
        float4 p1 = *(const float4*)(pred + (size_t)b * 2 * HW + HW + i0);
        int4   tg = *(const int4*)(target + (size_t)b * HW + i0);

        float p0a[4] = {p0.x, p0.y, p0.z, p0.w};
        float p1a[4] = {p1.x, p1.y, p1.z, p1.w};
        int   tga[4] = {tg.x, tg.y, tg.z, tg.w};

        u32 nib = 0;
        #pragma unroll
        for (int j = 0; j < 4; j++) {
            float d = tga[j] ? (p0a[j] - p1a[j]) : (p1a[j] - p0a[j]);  // p_other - p_t
            sumL[j] += __logf(1.0f + __expf(d));
            nib |= (p1a[j] > p0a[j] ? 1u : 0u) << j;
        }
        u32 hi = __shfl_down_sync(0xffffffffu, nib, 1);   // odd lane's nibble
        if ((t & 1) == 0) {
            int q = t >> 1;                                // byte index (8 pixels)
            ((unsigned char*)g_bits)[(size_t)b * 32768 + q] = (unsigned char)(nib | (hi << 4));
        }
    }
    *(float4*)(g_sumL + i0) = make_float4(sumL[0], sumL[1], sumL[2], sumL[3]);
}

// ---------------------------------------------------------------------------
// Kernel 2: ALL thinning in one launch. PDL: waits for k_prep before
// reading g_bits; independent prolog (indices, stamp init) runs early.
// ---------------------------------------------------------------------------
__global__ void __launch_bounds__(THIN_THREADS, 1) k_thin_all()
{
    __shared__ u64 buf0[THIN_THREADS];
    __shared__ u64 buf1[THIN_THREADS];
    __shared__ int stamp[TROWS + 2];   // stampOf(r) = stamp[r+1], init 0

    int img  = blockIdx.x >> 5;
    int band = blockIdx.x & 31;
    int t    = threadIdx.x;            // 0..639
    int r    = t >> 3;
    int wx   = t & 7;
    const u64* gb = g_bits + (size_t)img * 4096;

    if (t < TROWS + 2) stamp[t] = 0;   // independent prolog

    GRIDDEP_WAIT();                    // g_bits ready after this

    {
        int imr = band * 16 - 32 + r;
        u64 v = (imr >= 0 && imr < H) ? gb[imr * 8 + wx] : 0ULL;
        buf0[t] = v;
        if (r == 0 || r == TROWS - 1) buf1[t] = v;   // edge rows frozen in both buffers
    }
    __syncthreads();

    bool interior = (r >= 1 && r <= TROWS - 2);
    int base = r * 8 + wx;
    u64* fin = buf0;                   // final-state buffer (NSUB even -> buf0)

    #pragma unroll 1
    for (int s = 1; s <= NSUB; s++) {
        const u64* __restrict__ src = (s & 1) ? buf0 : buf1;
        u64* __restrict__ dst       = (s & 1) ? buf1 : buf0;
        bool FIRST = (s & 1);

        bool active = false;
        if (interior) {
            int a0 = stamp[r], a1 = stamp[r + 1], a2 = stamp[r + 2];
            active = (max(a0, max(a1, a2)) >= s - 2);   // parity-correct skip
        }
        if (!__syncthreads_or(active ? 1 : 0)) {        // whole tile converged
            fin = ((s - 1) & 1) ? buf1 : buf0;          // dst of substep s-1 (= state)
            break;
        }

        if (active) {
            u64 ctr = src[base];
            u64 cW = wx      ? src[base - 1] : 0ULL;
            u64 cE = wx < 7  ? src[base + 1] : 0ULL;
            u64 up = src[base - 8];
            u64 uW = wx      ? src[base - 9] : 0ULL;
            u64 uE = wx < 7  ? src[base - 7] : 0ULL;
            u64 dn = src[base + 8];
            u64 dW = wx      ? src[base + 7] : 0ULL;
            u64 dE = wx < 7  ? src[base + 9] : 0ULL;

            u64 P2 = up, P6 = dn;
            u64 P4 = (ctr >> 1) | (cE << 63);
            u64 P8 = (ctr << 1) | (cW >> 63);
            u64 P3 = (up  >> 1) | (uE << 63);
            u64 P9 = (up  << 1) | (uW >> 63);
            u64 P5 = (dn  >> 1) | (dE << 63);
            u64 P7 = (dn  << 1) | (dW >> 63);

            u64 x, y;
            x = P2 ^ P3;            u64 s1a = x ^ P4;  u64 c1a = (P2 & P3) | (P4 & x);
            x = P5 ^ P6;            u64 s1b = x ^ P7;  u64 c1b = (P5 & P6) | (P7 & x);
            x = s1a ^ s1b;          u64 s1c = x ^ P8;  u64 c1c = (s1a & s1b) | (P8 & x);
            u64 s0  = s1c ^ P9;     u64 c1d = s1c & P9;
            y = c1a ^ c1b;          u64 s2a = y ^ c1c; u64 c2a = (c1a & c1b) | (c1c & y);
            u64 sl1 = s2a ^ c1d;    u64 c2b = s2a & c1d;
            u64 sl2 = c2a ^ c2b;    u64 sl3 = c2a & c2b;

            u64 ge2 = sl1 | sl2 | sl3;
            u64 ge7 = sl3 | (sl2 & sl1 & s0);
            u64 in24 = ge2 & ~ge7;

            u64 t1 = ~P2 & P3, t2 = ~P3 & P4, t3 = ~P4 & P5, t4 = ~P5 & P6;
            u64 t5 = ~P6 & P7, t6 = ~P7 & P8, t7 = ~P8 & P9, t8 = ~P9 & P2;
            u64 acc = t1, multi = 0ULL;
            multi |= acc & t2; acc |= t2;
            multi |= acc & t3; acc |= t3;
            multi |= acc & t4; acc |= t4;
            multi |= acc & t5; acc |= t5;
            multi |= acc & t6; acc |= t6;
            multi |= acc & t7; acc |= t7;
            multi |= acc & t8; acc |= t8;
            u64 eq1 = acc & ~multi;

            u64 cc;
            if (FIRST) cc = ~(P2 & P4 & P6) & ~(P4 & P6 & P8);
            else       cc = ~(P2 & P4 & P8) & ~(P2 & P6 & P8);

            u64 rem = ctr & in24 & eq1 & cc;
            dst[base] = ctr ^ rem;
            if (rem) stamp[r + 1] = s;   // benign race (same value)
        }
        __syncthreads();
    }

    // output band = tile rows [32,48) of fin
    if (t < 128) {
        int rr = 32 + (t >> 3);
        int ww = t & 7;
        int imr = band * 16 + (t >> 3);
        g_bits2[(size_t)img * 4096 + imr * 8 + ww] = fin[rr * 8 + ww];
    }
}

// ---------------------------------------------------------------------------
// Kernel 3: warp-per-column capped vertical distance from bits -> g2 = d^2.
// PDL: waits for k_thin_all before reading g_bits2.
// ---------------------------------------------------------------------------
__global__ void k_vscan()
{
    int gw   = (blockIdx.x * blockDim.x + threadIdx.x) >> 5;  // 0..2047
    int lane = threadIdx.x & 31;
    int b = gw >> 9;
    int w = gw & (W - 1);
    const u64* __restrict__ bits = g_bits2 + (size_t)b * 4096;
    float* __restrict__ g2 = g_g2 + (size_t)b * HW;
    int wx = w >> 6, bi = w & 63;

    GRIDDEP_WAIT();                    // g_bits2 ready after this

    int base_row = lane * 16;
    int v[16];
    #pragma unroll
    for (int k = 0; k < 16; k++)
        v[k] = (int)((bits[(base_row + k) * 8 + wx] >> bi) & 1ULL);

    int ll = -100000;
    #pragma unroll
    for (int k = 0; k < 16; k++) if (v[k]) ll = base_row + k;
    int incl = ll;
    #pragma unroll
    for (int o = 1; o < 32; o <<= 1) {
        int x = __shfl_up_sync(0xffffffffu, incl, o);
        if (lane >= o) incl = max(incl, x);
    }
    int prefix = __shfl_up_sync(0xffffffffu, incl, 1);
    if (lane == 0) prefix = -100000;

    int lf = 100000;
    #pragma unroll
    for (int k = 15; k >= 0; k--) if (v[k]) lf = base_row + k;
    int incl2 = lf;
    #pragma unroll
    for (int o = 1; o < 32; o <<= 1) {
        int x = __shfl_down_sync(0xffffffffu, incl2, o);
        if (lane < 32 - o) incl2 = min(incl2, x);
    }
    int suffix = __shfl_down_sync(0xffffffffu, incl2, 1);
    if (lane == 31) suffix = 100000;

    int nxt[16];
    int cur = suffix;
    #pragma unroll
    for (int k = 15; k >= 0; k--) {
        int idx = base_row + k;
        if (v[k]) cur = idx;
        nxt[k] = cur;
    }
    int last = prefix;
    #pragma unroll
    for (int k = 0; k < 16; k++) {
        int idx = base_row + k;
        if (v[k]) last = idx;
        float fd = fminf((float)(idx - last), 1024.0f);
        float bd = fminf((float)(nxt[k] - idx), 1024.0f);
        float d  = fminf(fd, bd);
        g2[idx * W + w] = d * d;
    }
}

// ---------------------------------------------------------------------------
// Kernel 4: FUSED row EDT + LUT neighborhood + broadcast base + final sum.
// PDL: LUT build (independent) runs before the wait; staging after.
// Transitive completion: vscan-complete implies thin & prep complete, so the
// 2-hop reads of g_bits2 / g_sumL are safe.
// ---------------------------------------------------------------------------
__global__ void __launch_bounds__(256) k_edt_reduce(float* __restrict__ out)
{
    __shared__ float4 sg4[W];             // 8 KB: g2 row, batch-interleaved
    __shared__ u64    sbW[BB][3][9];      // west-shifted rows (+1 virtual word)
    __shared__ u32    lut[512];
    __shared__ double redB[8], redC[8], redD[8];
    __shared__ int    isLast;

    int h    = blockIdx.x >> 1;
    int half = blockIdx.x & 1;
    int t    = threadIdx.x;               // 0..255
    int w    = (half << 8) | t;           // this thread's pixel

    // independent prolog: 9-bit neighborhood LUT
    #pragma unroll
    for (int k = 0; k < 2; k++) {
        int key = t + k * 256;
        int s   = (key >> 4) & 1;
        int cnt = __popc(key) - s;
        int rh  = __popc(key & 0x38);
        int rv  = ((key >> 1) & 1) + s + ((key >> 7) & 1);
        int rd1 = (key & 1)        + s + ((key >> 8) & 1);
        int rd2 = ((key >> 2) & 1) + s + ((key >> 6) & 1);
        int dl  = abs(1 - rh) + abs(1 - rv) + abs(1 - rd1) + abs(1 - rd2);
        int e   = (s && (cnt == 1 || cnt >= 3)) ? 1 : 0;
        lut[key] = (u32)(cnt | (dl << 4) | (e << 8));
    }

    GRIDDEP_WAIT();                       // g_g2 (and transitively g_bits2/g_sumL) ready

    #pragma unroll
    for (int k = 0; k < 2; k++) {
        int q = t + k * 256;
        float4 g;
        g.x = g_g2[0 * HW + h * W + q];
        g.y = g_g2[1 * HW + h * W + q];
        g.z = g_g2[2 * HW + h * W + q];
        g.w = g_g2[3 * HW + h * W + q];
        sg4[q] = g;
    }
    if (t < 108) {
        int b = t / 27, rm = t % 27, rr = rm / 9, ww2 = rm % 9;
        int imr = h - 1 + rr;
        u64 m = 0, p = 0;
        if (imr >= 0 && imr < H) {
            const u64* rowp = g_bits2 + (size_t)b * 4096 + imr * 8;
            m = (ww2 < 8) ? rowp[ww2]     : 0ULL;
            p = (ww2 > 0) ? rowp[ww2 - 1] : 0ULL;
        }
        sbW[b][rr][ww2] = (m << 1) | (p >> 63);   // bit j = pixel j-1
    }
    __syncthreads();

    // interleaved 4-batch expanding-search EDT (per-batch fmin order bit-exact)
    float4 dd = sg4[w];
    {
        float m = fmaxf(fmaxf(dd.x, dd.y), fmaxf(dd.z, dd.w));
        for (int r = 1; r < W; r++) {
            float rr = (float)(r * r);
            if (rr >= m) break;
            int ql = w - r, qr = w + r;
            if (ql >= 0) {
                float4 v = sg4[ql];
                dd.x = fminf(dd.x, v.x + rr);
                dd.y = fminf(dd.y, v.y + rr);
                dd.z = fminf(dd.z, v.z + rr);
                dd.w = fminf(dd.w, v.w + rr);
            }
            if (qr < W) {
                float4 v = sg4[qr];
                dd.x = fminf(dd.x, v.x + rr);
                dd.y = fminf(dd.y, v.y + rr);
                dd.z = fminf(dd.z, v.z + rr);
                dd.w = fminf(dd.w, v.w + rr);
            }
            m = fmaxf(fmaxf(dd.x, dd.y), fmaxf(dd.z, dd.w));
        }
    }
    float wex[4] = { __expf(sqrtf(dd.x) * -0.05f), __expf(sqrtf(dd.y) * -0.05f),
                     __expf(sqrtf(dd.z) * -0.05f), __expf(sqrtf(dd.w) * -0.05f) };

    int wx = w >> 6, bi = w & 63;
    float sumW = 0.0f;
    int contI = 0, dirlI = 0;

    #pragma unroll
    for (int b = 0; b < BB; b++) {
        int key;
        u64 uW = sbW[b][0][wx], cW = sbW[b][1][wx], dW = sbW[b][2][wx];
        if (bi < 62) {
            key = (int)((uW >> bi) & 7)
                | ((int)((cW >> bi) & 7) << 3)
                | ((int)((dW >> bi) & 7) << 6);
        } else {
            u64 uN = sbW[b][0][wx + 1], cN = sbW[b][1][wx + 1], dN = sbW[b][2][wx + 1];
            int sh2 = 64 - bi;   // 1 or 2
            key = (int)(((uW >> bi) | (uN << sh2)) & 7)
                | ((int)(((cW >> bi) | (cN << sh2)) & 7) << 3)
                | ((int)(((dW >> bi) | (dN << sh2)) & 7) << 6);
        }
        u32 v = lut[key];
        contI += (int)(v & 15);
        dirlI += (int)((v >> 4) & 15);
        sumW  += wex[b] + ((v & 256) ? 20.0f : 0.0f);
    }

    double sb = (double)sumW * (double)g_sumL[h * W + w];
    unsigned fm = 0xffffffffu;
    double sc = (double)contI, sd = (double)dirlI;
    #pragma unroll
    for (int o = 16; o > 0; o >>= 1) {
        sb += __shfl_down_sync(fm, sb, o);
        sc += __shfl_down_sync(fm, sc, o);
        sd += __shfl_down_sync(fm, sd, o);
    }
    int wid = t >> 5, lane = t & 31;
    if (lane == 0) { redB[wid] = sb; redC[wid] = sc; redD[wid] = sd; }
    __syncthreads();
    if (wid == 0) {
        double b2 = (lane < 8) ? redB[lane] : 0.0;
        double c2 = (lane < 8) ? redC[lane] : 0.0;
        double d2 = (lane < 8) ? redD[lane] : 0.0;
        #pragma unroll
        for (int o = 4; o > 0; o >>= 1) {
            b2 += __shfl_down_sync(fm, b2, o);
            c2 += __shfl_down_sync(fm, c2, o);
            d2 += __shfl_down_sync(fm, d2, o);
        }
        if (lane == 0) {
            g_partB[blockIdx.x] = b2;
            g_partC[blockIdx.x] = (int)c2;
            g_partD[blockIdx.x] = (int)d2;
            __threadfence();
            int old = atomicAdd(&g_ctr, 1);
            isLast = (old == EDT_BLOCKS - 1) ? 1 : 0;
        }
    }
    __syncthreads();

    if (isLast) {   // last block: deterministic fixed-order final sum
        __threadfence();
        double b3 = 0.0, c3 = 0.0, d3 = 0.0;
        #pragma unroll
        for (int k = 0; k < 4; k++) {
            int i = t + k * 256;
            b3 += g_partB[i];
            c3 += (double)g_partC[i];
            d3 += (double)g_partD[i];
        }
        #pragma unroll
        for (int o = 16; o > 0; o >>= 1) {
            b3 += __shfl_down_sync(fm, b3, o);
            c3 += __shfl_down_sync(fm, c3, o);
            d3 += __shfl_down_sync(fm, d3, o);
        }
        if (lane == 0) { redB[wid] = b3; redC[wid] = c3; redD[wid] = d3; }
        __syncthreads();
        if (wid == 0) {
            double b4 = (lane < 8) ? redB[lane] : 0.0;
            double c4 = (lane < 8) ? redC[lane] : 0.0;
            double d4 = (lane < 8) ? redD[lane] : 0.0;
            #pragma unroll
            for (int o = 4; o > 0; o >>= 1) {
                b4 += __shfl_down_sync(fm, b4, o);
                c4 += __shfl_down_sync(fm, c4, o);
                d4 += __shfl_down_sync(fm, d4, o);
            }
            if (lane == 0) {
                double base = b4 / (double)((double)BB * BB * HW);
                double cont = c4 / (double)NPIX;
                double dirl = d4 / (double)NPIX;
                out[0] = (float)(base + 0.3 * cont + 0.5 * dirl);
                g_ctr = 0;   // reset for next graph replay
            }
        }
    }
}

// ---------------------------------------------------------------------------
// Launch helper: programmatic stream serialization (PDL) on the chain edges.
// ---------------------------------------------------------------------------
static inline void launch_pdl(void (*kern)(), dim3 grid, dim3 block)
{
    cudaLaunchConfig_t cfg = {};
    cfg.gridDim = grid;
    cfg.blockDim = block;
    cfg.dynamicSmemBytes = 0;
    cfg.stream = 0;
    cudaLaunchAttribute attr[1];
    attr[0].id = cudaLaunchAttributeProgrammaticStreamSerialization;
    attr[0].val.programmaticStreamSerializationAllowed = 1;
    cfg.attrs = attr;
    cfg.numAttrs = 1;
    cudaLaunchKernelEx(&cfg, kern);
}

extern "C" void kernel_launch(void* const* d_in, const int* in_sizes, int n_in,
                              void* d_out, int out_size)
{
    const float* pred   = (const float*)d_in[0];
    const int*   target = (const int*)d_in[1];

    // prep: normal launch (full serialization against previous replay's edt)
    k_prep<<<256, 256>>>(pred, target);

    // thin, vscan: PDL edges
    launch_pdl(k_thin_all, dim3(128), dim3(THIN_THREADS));
    launch_pdl(k_vscan,    dim3(256), dim3(256));

    // edt_reduce: PDL edge, takes an argument
    {
        cudaLaunchConfig_t cfg = {};
        cfg.gridDim = dim3(EDT_BLOCKS);
        cfg.blockDim = dim3(256);
        cfg.dynamicSmemBytes = 0;
        cfg.stream = 0;
        cudaLaunchAttribute attr[1];
        attr[0].id = cudaLaunchAttributeProgrammaticStreamSerialization;
        attr[0].val.programmaticStreamSerializationAllowed = 1;
        cfg.attrs = attr;
        cfg.numAttrs = 1;
        float* outp = (float*)d_out;
        cudaLaunchKernelEx(&cfg, k_edt_reduce, outp);
    }
}